// round 6
// baseline (speedup 1.0000x reference)
#include <cuda_runtime.h>
#include <cuda_bf16.h>

// VanillaRNN diagonal recurrence. MUFU-port-bound at ~113.5K cyc/SMSP floor.
// Pipe-balancing: 1 of every 12 tanh evaluations is computed entirely on the
// FMA/ALU pipes (exp2 bit-trick + Taylor 2^r + Newton rcp, ~5e-6 abs err),
// the rest on MUFU (tanh.approx). Deterministic per-thread interleave keeps
// every SMSP's MUFU/FMA load identical. All math f32 (f16 state fatal, R4).

#define RB 1024   // batch
#define RT 1024   // time steps
#define RH 256    // hidden
#define RC 10     // classes

__device__ __forceinline__ float tanh_hw(float x) {
    float r;
    asm("tanh.approx.f32 %0, %1;" : "=f"(r) : "f"(x));
    return r;
}

// All-FMA/ALU tanh, no MUFU. |err| ~5e-6 abs.
// tanh(z) = sign(z) * (1 - 2e/(1+e)),  e = exp(-2|z|) = 2^w, w = -2|z|/ln2.
__device__ __forceinline__ float tanh_fma(float z) {
    const float NL2E2 = -2.885390081777927f;   // -2/ln2
    const float MAGIC = 12582912.0f;           // 1.5 * 2^23
    float az = fminf(fabsf(z), 9.0f);          // tanh(9)=1-3e-8; keeps k in range
    float t  = fmaf(az, NL2E2, MAGIC);         // w rounded-to-nearest lives in t
    float kf = t - MAGIC;                      // k = rint(w), k in [-26, 0]
    float r  = fmaf(az, NL2E2, -kf);           // r = w - k, in [-0.5, 0.5]
    int   ki = __float_as_int(t) - 0x4B400000; // integer k via mantissa bits
    float sc = __int_as_float((ki + 127) << 23); // 2^k (exponent-only float)
    // 2^r, Taylor degree-5 (rel err < 2.4e-6 on [-0.5,0.5])
    float p = 1.33335581464e-3f;
    p = fmaf(p, r, 9.61812910763e-3f);
    p = fmaf(p, r, 5.55041086648e-2f);
    p = fmaf(p, r, 2.40226506959e-1f);
    p = fmaf(p, r, 6.93147180560e-1f);
    p = fmaf(p, r, 1.0f);
    float e   = p * sc;                        // e^{-2|z|} in (2^-26, 1]
    float den = 1.0f + e;                      // [1, 2]
    // 1/den: minimax linear seed (err 4.3%) + 2 Newton -> ~3.4e-6 rel
    float y = fmaf(den, -0.5f, 1.45710678f);
    y = y * fmaf(-den, y, 2.0f);
    y = y * fmaf(-den, y, 2.0f);
    float res = fmaf(-2.0f * e, y, 1.0f);      // 1 - 2e/(1+e) = tanh(|z|)
    return copysignf(res, z);
}

__global__ __launch_bounds__(RH, 7)
void vanilla_rnn_kernel(const float* __restrict__ x,
                        const float* __restrict__ W_hx,
                        const float* __restrict__ W_hh,
                        const float* __restrict__ b_h,
                        const float* __restrict__ W_hp,
                        const float* __restrict__ b_o,
                        float* __restrict__ out)
{
    __shared__ float4 xs4[RT / 4];   // this block's x row (4 KB)
    __shared__ float  hs[RH];        // final hidden state for epilogue

    const int b = blockIdx.x;
    const int h = threadIdx.x;

    {
        const float4* xrow = reinterpret_cast<const float4*>(x + (size_t)b * RT);
        xs4[h] = xrow[h];
    }

    const float wi = W_hx[h];
    const float wd = W_hh[h * RH + h];
    const float bh = b_h[h];

    __syncthreads();

    float hv = 0.0f;
    // 85 chunks of 12 steps (3 float4 loads): 11 MUFU-tanh + 1 FMA-tanh.
    // beta = 85/1024 ~= 0.083 balances MUFU (104K cyc) vs FMA (97K cyc)/SMSP.
    #pragma unroll 1
    for (int c = 0; c < 85; c++) {
        const int q = c * 3;
        float4 xa = xs4[q + 0];
        float4 xb = xs4[q + 1];
        float4 xc = xs4[q + 2];
        float a0 = fmaf(xa.x, wi, bh), a1 = fmaf(xa.y, wi, bh);
        float a2 = fmaf(xa.z, wi, bh), a3 = fmaf(xa.w, wi, bh);
        float a4 = fmaf(xb.x, wi, bh), a5 = fmaf(xb.y, wi, bh);
        float a6 = fmaf(xb.z, wi, bh), a7 = fmaf(xb.w, wi, bh);
        float a8 = fmaf(xc.x, wi, bh), a9 = fmaf(xc.y, wi, bh);
        float aA = fmaf(xc.z, wi, bh), aB = fmaf(xc.w, wi, bh);
        hv = tanh_hw (fmaf(hv, wd, a0));
        hv = tanh_hw (fmaf(hv, wd, a1));
        hv = tanh_hw (fmaf(hv, wd, a2));
        hv = tanh_hw (fmaf(hv, wd, a3));
        hv = tanh_hw (fmaf(hv, wd, a4));
        hv = tanh_hw (fmaf(hv, wd, a5));
        hv = tanh_hw (fmaf(hv, wd, a6));
        hv = tanh_hw (fmaf(hv, wd, a7));
        hv = tanh_hw (fmaf(hv, wd, a8));
        hv = tanh_hw (fmaf(hv, wd, a9));
        hv = tanh_hw (fmaf(hv, wd, aA));
        hv = tanh_fma(fmaf(hv, wd, aB));   // FMA-pipe step
    }
    // tail: steps 1020..1023
    {
        float4 xa = xs4[255];
        hv = tanh_hw(fmaf(hv, wd, fmaf(xa.x, wi, bh)));
        hv = tanh_hw(fmaf(hv, wd, fmaf(xa.y, wi, bh)));
        hv = tanh_hw(fmaf(hv, wd, fmaf(xa.z, wi, bh)));
        hv = tanh_hw(fmaf(hv, wd, fmaf(xa.w, wi, bh)));
    }

    hs[h] = hv;
    __syncthreads();

    if (h < RC) {
        const float* wrow = W_hp + h * RH;
        float acc = b_o[h];
        #pragma unroll 8
        for (int j = 0; j < RH; j++)
            acc = fmaf(hs[j], wrow[j], acc);
        out[b * RC + h] = acc;
    }
}

extern "C" void kernel_launch(void* const* d_in, const int* in_sizes, int n_in,
                              void* d_out, int out_size)
{
    const float* x    = (const float*)d_in[0];
    const float* W_hx = (const float*)d_in[1];
    const float* W_hh = (const float*)d_in[2];
    const float* b_h  = (const float*)d_in[3];
    const float* W_hp = (const float*)d_in[4];
    const float* b_o  = (const float*)d_in[5];
    float* out = (float*)d_out;

    vanilla_rnn_kernel<<<RB, RH>>>(x, W_hx, W_hh, b_h, W_hp, b_o, out);
}

// round 7
// speedup vs baseline: 1.0330x; 1.0330x over previous
#include <cuda_runtime.h>
#include <cuda_bf16.h>

// VanillaRNN diagonal recurrence, f32. MUFU-port-bound (~114K cyc/SMSP floor).
// Pipe-balancing v2: 2 of every 20 tanh steps run on the FMA pipe via a LEAN
// 15-FMA tanh (deg-4 Estrin exp2 + bit-trick scale on ALU pipe + linear-seed
// 2-Newton reciprocal). beta=0.1 -> MUFU 7.2 cyc/step, FMA 7.0 cyc/step.
// f16 state is fatal (R4); all state f32.

#define RB 1024   // batch
#define RT 1024   // time steps
#define RH 256    // hidden
#define RC 10     // classes

__device__ __forceinline__ float tanh_hw(float x) {
    float r;
    asm("tanh.approx.f32 %0, %1;" : "=f"(r) : "f"(x));
    return r;
}

// Lean all-FMA/ALU tanh: ~15 FMA-pipe + 4 ALU-pipe ops, |err| ~4e-6 abs.
// tanh(z) = sign(z)*(1 - 2e/(1+e)), e = 2^w, w = -2|z|/ln2 = k + r.
__device__ __forceinline__ float tanh_fma(float z) {
    const float NL2E2 = -2.885390081777927f;   // -2/ln2
    const float MAGIC = 12582912.0f;           // 1.5 * 2^23
    float az = fminf(fabsf(z), 40.0f);         // FMNMX (alu), |.| folds
    float t  = fmaf(az, NL2E2, MAGIC);         // w rounded lives in low bits
    float kf = t - MAGIC;                      // k = rint(w)
    float r  = fmaf(az, NL2E2, -kf);           // r in [-0.5, 0.5]
    // sc = 2^k from integer bits: as_int(t) = 0x4B400000 + k
    float sc = __int_as_float((__float_as_int(t) + (127 - 0x4B400000)) << 23);
    // 2^r Taylor deg-4, Estrin (rel err < 4.2e-5)
    float r2 = r * r;
    float q0 = fmaf(0.6931471806f, r, 1.0f);
    float q1 = fmaf(0.0555041087f, r, 0.2402265070f);
    float qq = fmaf(0.0096181291f, r2, q1);
    float p  = fmaf(qq, r2, q0);
    float e  = p * sc;                         // e^{-2|z|} in (0, 1]
    float den = e + 1.0f;                      // [1, 2]
    float y  = fmaf(den, -0.5f, 1.45710678f);  // linear seed (4.3%)
    y = y * fmaf(-den, y, 2.0f);               // Newton 1
    y = y * fmaf(-den, y, 2.0f);               // Newton 2 -> ~3e-6 rel
    float e2 = e + e;                          // off critical path
    float res = fmaf(-e2, y, 1.0f);            // 1 - 2e/(1+e)
    return copysignf(res, z);                  // LOP3 (alu)
}

__global__ __launch_bounds__(RH, 7)
void vanilla_rnn_kernel(const float* __restrict__ x,
                        const float* __restrict__ W_hx,
                        const float* __restrict__ W_hh,
                        const float* __restrict__ b_h,
                        const float* __restrict__ W_hp,
                        const float* __restrict__ b_o,
                        float* __restrict__ out)
{
    __shared__ float4 xs4[RT / 4];   // this block's x row (4 KB)
    __shared__ float  hs[RH];        // final hidden state for epilogue

    const int b = blockIdx.x;
    const int h = threadIdx.x;

    {
        const float4* xrow = reinterpret_cast<const float4*>(x + (size_t)b * RT);
        xs4[h] = xrow[h];
    }

    const float wi = W_hx[h];
    const float wd = W_hh[h * RH + h];
    const float bh = b_h[h];

    __syncthreads();

    float hv = 0.0f;
    // 51 chunks x 20 steps (5 float4 loads). Offload steps 11 and 19 of each
    // chunk to the FMA pipe -> beta = 2/20 = 0.1, uniform on every SMSP.
    #pragma unroll 1
    for (int c = 0; c < 51; c++) {
        const int q = c * 5;
        #pragma unroll
        for (int s = 0; s < 5; s++) {
            float4 xv = xs4[q + s];
            float a0 = fmaf(xv.x, wi, bh);
            float a1 = fmaf(xv.y, wi, bh);
            float a2 = fmaf(xv.z, wi, bh);
            float a3 = fmaf(xv.w, wi, bh);
            hv = tanh_hw(fmaf(hv, wd, a0));
            hv = tanh_hw(fmaf(hv, wd, a1));
            hv = tanh_hw(fmaf(hv, wd, a2));
            if (s == 2 || s == 4)
                hv = tanh_fma(fmaf(hv, wd, a3));   // FMA-pipe step
            else
                hv = tanh_hw(fmaf(hv, wd, a3));
        }
    }
    // tail: steps 1020..1023 (MUFU)
    {
        float4 xv = xs4[255];
        hv = tanh_hw(fmaf(hv, wd, fmaf(xv.x, wi, bh)));
        hv = tanh_hw(fmaf(hv, wd, fmaf(xv.y, wi, bh)));
        hv = tanh_hw(fmaf(hv, wd, fmaf(xv.z, wi, bh)));
        hv = tanh_hw(fmaf(hv, wd, fmaf(xv.w, wi, bh)));
    }

    hs[h] = hv;
    __syncthreads();

    if (h < RC) {
        const float* wrow = W_hp + h * RH;
        float acc = b_o[h];
        #pragma unroll 8
        for (int j = 0; j < RH; j++)
            acc = fmaf(hs[j], wrow[j], acc);
        out[b * RC + h] = acc;
    }
}

extern "C" void kernel_launch(void* const* d_in, const int* in_sizes, int n_in,
                              void* d_out, int out_size)
{
    const float* x    = (const float*)d_in[0];
    const float* W_hx = (const float*)d_in[1];
    const float* W_hh = (const float*)d_in[2];
    const float* b_h  = (const float*)d_in[3];
    const float* W_hp = (const float*)d_in[4];
    const float* b_o  = (const float*)d_in[5];
    float* out = (float*)d_out;

    vanilla_rnn_kernel<<<RB, RH>>>(x, W_hx, W_hh, b_h, W_hp, b_o, out);
}